// round 8
// baseline (speedup 1.0000x reference)
#include <cuda_runtime.h>
#include <math.h>

#define HID 128
#define NI_MAX 20000
#define NT_MAX 100000
#define NE_MAX 600000

// ---------------- scratch (device globals; no allocation allowed) ----------
__device__ float g_hs[NI_MAX * HID];   // projected ingredient features
__device__ float g_asrc[NI_MAX];       // per-src attention logit part
__device__ int   g_srcs[NE_MAX];       // CSR: source node per slot (dst-grouped)
__device__ int   g_deg[NT_MAX];        // in-degree per dst
__device__ int   g_off[NT_MAX + 1];    // CSR offsets
__device__ int   g_cursor[NT_MAX];     // fill cursors
__device__ float g_v[HID];             // W_taste^T @ att_dst
__device__ float g_c;                  // b_taste . att_dst
__device__ float g_colsum[HID];        // BN column sums
__device__ float g_colsq[HID];         // BN column sum of squares

// ---------------- init: zero counters --------------------------------------
__global__ void k_init(int nt) {
    int stride = gridDim.x * blockDim.x;
    for (int i = blockIdx.x * blockDim.x + threadIdx.x; i < nt; i += stride) {
        g_deg[i] = 0;
        g_cursor[i] = 0;
        if (i < HID) { g_colsum[i] = 0.0f; g_colsq[i] = 0.0f; }
    }
}

// ---------------- v = W_taste^T att_dst ; c = b_taste . att_dst ------------
__global__ void k_v(const float* __restrict__ Wt, const float* __restrict__ bt,
                    const float* __restrict__ att_dst) {
    int k = threadIdx.x; // 128 threads
    float s = 0.0f;
    #pragma unroll 8
    for (int j = 0; j < HID; j++) s += att_dst[j] * Wt[j * HID + k];
    g_v[k] = s;
    if (k == 0) {
        float c = 0.0f;
        for (int j = 0; j < HID; j++) c += att_dst[j] * bt[j];
        g_c = c;
    }
}

// ---------------- hs = x_ing @ W_ing^T + b_ing, fused a_src ----------------
// blockDim = 128 (one thread per output column), 16 rows per block
__global__ void k_hs(const float* __restrict__ x, const float* __restrict__ W,
                     const float* __restrict__ b, const float* __restrict__ att_src,
                     int ni) {
    __shared__ float Ws[32][129];
    __shared__ float xs[16][33];
    __shared__ float red[4][16];
    const int c = threadIdx.x;
    const int row0 = blockIdx.x * 16;
    float acc[16];
    #pragma unroll
    for (int r = 0; r < 16; r++) acc[r] = 0.0f;

    for (int kt = 0; kt < 4; kt++) {
        #pragma unroll
        for (int i = 0; i < 32; i++) {
            int f = threadIdx.x + i * 128;
            int cc = f >> 5, kk = f & 31;
            Ws[kk][cc] = W[cc * HID + kt * 32 + kk];
        }
        #pragma unroll
        for (int i = 0; i < 4; i++) {
            int f = threadIdx.x + i * 128;
            int r = f >> 5, kk = f & 31;
            int row = row0 + r;
            xs[r][kk] = (row < ni) ? x[row * HID + kt * 32 + kk] : 0.0f;
        }
        __syncthreads();
        #pragma unroll
        for (int kk = 0; kk < 32; kk++) {
            float w = Ws[kk][c];
            #pragma unroll
            for (int r = 0; r < 16; r++) acc[r] += xs[r][kk] * w;
        }
        __syncthreads();
    }
    const float bb = b[c];
    const float as = att_src[c];
    const int lane = c & 31, wid = c >> 5;
    #pragma unroll
    for (int r = 0; r < 16; r++) {
        int row = row0 + r;
        float val = acc[r] + bb;
        if (row < ni) g_hs[row * HID + c] = val;
        float s = val * as;
        #pragma unroll
        for (int o = 16; o; o >>= 1) s += __shfl_xor_sync(0xffffffffu, s, o);
        if (lane == 0) red[wid][r] = s;
    }
    __syncthreads();
    if (c < 16) {
        int row = row0 + c;
        if (row < ni)
            g_asrc[row] = red[0][c] + red[1][c] + red[2][c] + red[3][c];
    }
}

// ---------------- CSR build: count ------------------------------------------
__global__ void k_count(const int* __restrict__ dst, int ne) {
    int i = blockIdx.x * blockDim.x + threadIdx.x;
    if (i < ne) atomicAdd(&g_deg[dst[i]], 1);
}

// ---------------- CSR build: exclusive scan (single block, 1024 threads) ----
__global__ void k_scan(int nt) {
    __shared__ int part[1024];
    const int t = threadIdx.x;
    const int C = (nt + 1023) / 1024;
    const int lo = t * C;
    const int hi = min(lo + C, nt);
    int s = 0;
    for (int i = lo; i < hi; i++) s += g_deg[i];
    part[t] = s;
    __syncthreads();
    // Hillis-Steele inclusive scan
    for (int o = 1; o < 1024; o <<= 1) {
        int v = (t >= o) ? part[t - o] : 0;
        __syncthreads();
        part[t] += v;
        __syncthreads();
    }
    int run = part[t] - s;  // exclusive base for this chunk
    for (int i = lo; i < hi; i++) {
        g_off[i] = run;
        run += g_deg[i];
    }
    if (t == 1023) g_off[nt] = part[1023];
}

// ---------------- CSR build: fill (store src node per slot) -----------------
__global__ void k_fill(const int* __restrict__ src, const int* __restrict__ dst, int ne) {
    int i = blockIdx.x * blockDim.x + threadIdx.x;
    if (i >= ne) return;
    int d = dst[i];
    int slot = atomicAdd(&g_cursor[d], 1);
    g_srcs[g_off[d] + slot] = src[i];
}

// ---------------- mega: per-dst softmax + aggregate + relu + residual + BN --
// Persistent grid-stride: blockDim = 256 (8 warps), one dst per warp per
// iteration. BN partials accumulate in registers across ALL dsts a lane
// touches; one shared-reduce + one atomic set per block at the end.
// Softmax shift-invariance: logits bounded (~|9|), exp safely in float range,
// so no max-subtraction needed -> single pass, edge state held in registers.
#define MEGA_WARPS 8
#define MEGA_BLOCKS 1184
__global__ void k_mega(const float* __restrict__ x_taste,
                       float* __restrict__ out_taste, int nt) {
    __shared__ float4 ssum[MEGA_WARPS][32];
    __shared__ float4 ssq[MEGA_WARPS][32];
    const int lane = threadIdx.x & 31;
    const int wid  = threadIdx.x >> 5;
    const int gw   = blockIdx.x * MEGA_WARPS + wid;     // global warp id
    const int nw   = gridDim.x * MEGA_WARPS;            // total warps

    // hs base for this lane's float4 column
    const float4* __restrict__ hs4 =
        reinterpret_cast<const float4*>(g_hs) + lane;

    float4 bsum = make_float4(0.f, 0.f, 0.f, 0.f);
    float4 bsq  = make_float4(0.f, 0.f, 0.f, 0.f);

    for (int d = gw; d < nt; d += nw) {
        // a_dst = x_taste[d] . v + c
        float4 xt = reinterpret_cast<const float4*>(x_taste + (size_t)d * HID)[lane];
        float4 vv = reinterpret_cast<const float4*>(g_v)[lane];
        float ad = xt.x * vv.x + xt.y * vv.y + xt.z * vv.z + xt.w * vv.w;
        #pragma unroll
        for (int o = 16; o; o >>= 1) ad += __shfl_xor_sync(0xffffffffu, ad, o);
        ad += g_c;

        const int beg = g_off[d];
        const int deg = g_off[d + 1] - beg;

        float4 acc = make_float4(0.f, 0.f, 0.f, 0.f);

        if (deg <= 32) {
            // register-resident path (covers ~all nodes; mean degree ~6)
            int   s  = 0;
            float ev = 0.0f;
            if (lane < deg) {
                s = g_srcs[beg + lane];
                float a = g_asrc[s] + ad;
                a = (a >= 0.0f) ? a : 0.2f * a;      // leaky_relu(0.2)
                ev = expf(a);
            }
            float denom = ev;
            #pragma unroll
            for (int o = 16; o; o >>= 1) denom += __shfl_xor_sync(0xffffffffu, denom, o);
            const float inv = 1.0f / (denom + 1e-16f);

            // 4-way batched gather: 4 independent LDG.128 in flight per iter
            int j = 0;
            for (; j + 4 <= deg; j += 4) {
                float w0 = __shfl_sync(0xffffffffu, ev, j + 0) * inv;
                float w1 = __shfl_sync(0xffffffffu, ev, j + 1) * inv;
                float w2 = __shfl_sync(0xffffffffu, ev, j + 2) * inv;
                float w3 = __shfl_sync(0xffffffffu, ev, j + 3) * inv;
                int   s0 = __shfl_sync(0xffffffffu, s, j + 0);
                int   s1 = __shfl_sync(0xffffffffu, s, j + 1);
                int   s2 = __shfl_sync(0xffffffffu, s, j + 2);
                int   s3 = __shfl_sync(0xffffffffu, s, j + 3);
                float4 h0 = hs4[(size_t)s0 * (HID / 4)];
                float4 h1 = hs4[(size_t)s1 * (HID / 4)];
                float4 h2 = hs4[(size_t)s2 * (HID / 4)];
                float4 h3 = hs4[(size_t)s3 * (HID / 4)];
                acc.x += w0 * h0.x; acc.y += w0 * h0.y; acc.z += w0 * h0.z; acc.w += w0 * h0.w;
                acc.x += w1 * h1.x; acc.y += w1 * h1.y; acc.z += w1 * h1.z; acc.w += w1 * h1.w;
                acc.x += w2 * h2.x; acc.y += w2 * h2.y; acc.z += w2 * h2.z; acc.w += w2 * h2.w;
                acc.x += w3 * h3.x; acc.y += w3 * h3.y; acc.z += w3 * h3.z; acc.w += w3 * h3.w;
            }
            for (; j < deg; j++) {
                float w  = __shfl_sync(0xffffffffu, ev, j) * inv;
                int   sj = __shfl_sync(0xffffffffu, s, j);
                float4 h = hs4[(size_t)sj * (HID / 4)];
                acc.x += w * h.x; acc.y += w * h.y;
                acc.z += w * h.z; acc.w += w * h.w;
            }
        } else {
            // rare fallback: recompute exp (redundant across lanes, cheap)
            float denom = 0.0f;
            for (int k = beg + lane; k < beg + deg; k += 32) {
                float a = g_asrc[g_srcs[k]] + ad;
                a = (a >= 0.0f) ? a : 0.2f * a;
                denom += expf(a);
            }
            #pragma unroll
            for (int o = 16; o; o >>= 1) denom += __shfl_xor_sync(0xffffffffu, denom, o);
            const float inv = 1.0f / (denom + 1e-16f);

            for (int k = beg; k < beg + deg; k++) {
                int sj = g_srcs[k];                  // broadcast
                float a = g_asrc[sj] + ad;           // broadcast
                a = (a >= 0.0f) ? a : 0.2f * a;
                float w = expf(a) * inv;
                float4 h = hs4[(size_t)sj * (HID / 4)];
                acc.x += w * h.x; acc.y += w * h.y;
                acc.z += w * h.z; acc.w += w * h.w;
            }
        }

        // relu(agg) + residual, write
        float4 outv;
        outv.x = fmaxf(acc.x, 0.f) + xt.x;
        outv.y = fmaxf(acc.y, 0.f) + xt.y;
        outv.z = fmaxf(acc.z, 0.f) + xt.z;
        outv.w = fmaxf(acc.w, 0.f) + xt.w;
        reinterpret_cast<float4*>(out_taste + (size_t)d * HID)[lane] = outv;

        // BN partials (register-resident across the whole loop)
        bsum.x += outv.x; bsum.y += outv.y; bsum.z += outv.z; bsum.w += outv.w;
        bsq.x += outv.x * outv.x; bsq.y += outv.y * outv.y;
        bsq.z += outv.z * outv.z; bsq.w += outv.w * outv.w;
    }

    // block-level BN reduce: shared across the 8 warps, one atomic set/block
    ssum[wid][lane] = bsum;
    ssq[wid][lane]  = bsq;
    __syncthreads();
    if (wid == 0) {
        float4 s = make_float4(0.f, 0.f, 0.f, 0.f);
        float4 q = make_float4(0.f, 0.f, 0.f, 0.f);
        #pragma unroll
        for (int i = 0; i < MEGA_WARPS; i++) {
            float4 a = ssum[i][lane], b = ssq[i][lane];
            s.x += a.x; s.y += a.y; s.z += a.z; s.w += a.w;
            q.x += b.x; q.y += b.y; q.z += b.z; q.w += b.w;
        }
        atomicAdd(&g_colsum[lane * 4 + 0], s.x);
        atomicAdd(&g_colsum[lane * 4 + 1], s.y);
        atomicAdd(&g_colsum[lane * 4 + 2], s.z);
        atomicAdd(&g_colsum[lane * 4 + 3], s.w);
        atomicAdd(&g_colsq[lane * 4 + 0], q.x);
        atomicAdd(&g_colsq[lane * 4 + 1], q.y);
        atomicAdd(&g_colsq[lane * 4 + 2], q.z);
        atomicAdd(&g_colsq[lane * 4 + 3], q.w);
    }
}

// ---------------- taste pass B: BN normalize + affine + relu ---------------
#define ROWS_B 128
__global__ void k_tasteB(const float* __restrict__ gamma, const float* __restrict__ beta,
                         float4* __restrict__ out4, int nt) {
    const int f4 = threadIdx.x & 31;
    const int rl = threadIdx.x >> 5;
    const float inv_n = 1.0f / (float)nt;
    float mean[4], scale[4], bet[4];
    #pragma unroll
    for (int k = 0; k < 4; k++) {
        int f = f4 * 4 + k;
        float m = g_colsum[f] * inv_n;
        float var = g_colsq[f] * inv_n - m * m;
        mean[k] = m;
        scale[k] = rsqrtf(var + 1e-5f) * gamma[f];
        bet[k] = beta[f];
    }
    const int rend = min(blockIdx.x * ROWS_B + ROWS_B, nt);
    for (int r = blockIdx.x * ROWS_B + rl; r < rend; r += 8) {
        int idx = r * (HID / 4) + f4;
        float4 v = out4[idx];
        v.x = fmaxf((v.x - mean[0]) * scale[0] + bet[0], 0.f);
        v.y = fmaxf((v.y - mean[1]) * scale[1] + bet[1], 0.f);
        v.z = fmaxf((v.z - mean[2]) * scale[2] + bet[2], 0.f);
        v.w = fmaxf((v.w - mean[3]) * scale[3] + bet[3], 0.f);
        out4[idx] = v;
    }
}

// ---------------- launch ---------------------------------------------------
extern "C" void kernel_launch(void* const* d_in, const int* in_sizes, int n_in,
                              void* d_out, int out_size) {
    const float* x_ing   = (const float*)d_in[0];
    const float* x_taste = (const float*)d_in[1];
    const int*   esrc    = (const int*)d_in[2];
    const int*   edst    = (const int*)d_in[3];
    const float* Wi      = (const float*)d_in[4];
    const float* bi      = (const float*)d_in[5];
    const float* Wt      = (const float*)d_in[6];
    const float* bt      = (const float*)d_in[7];
    const float* att_src = (const float*)d_in[8];
    const float* att_dst = (const float*)d_in[9];
    // d_in[10..12] = k_lin_w, k_lin_b, q_sem: provably unused (beta == 1)
    const float* gamma   = (const float*)d_in[13];
    const float* beta    = (const float*)d_in[14];

    const int ni = in_sizes[0] / HID;
    const int nt = in_sizes[1] / HID;
    const int ne = in_sizes[2];

    float* out       = (float*)d_out;
    float* out_taste = out + (size_t)ni * HID;

    // ingredient passthrough
    cudaMemcpyAsync(out, x_ing, (size_t)ni * HID * sizeof(float),
                    cudaMemcpyDeviceToDevice);

    k_init  <<<(nt + 255) / 256, 256>>> (nt);
    k_v     <<<1, 128>>> (Wt, bt, att_dst);
    k_hs    <<<(ni + 15) / 16, 128>>> (x_ing, Wi, bi, att_src, ni);
    k_count <<<(ne + 255) / 256, 256>>> (edst, ne);
    k_scan  <<<1, 1024>>> (nt);
    k_fill  <<<(ne + 255) / 256, 256>>> (esrc, edst, ne);
    k_mega  <<<MEGA_BLOCKS, 256>>> (x_taste, out_taste, nt);
    k_tasteB<<<(nt + ROWS_B - 1) / ROWS_B, 256>>> (gamma, beta,
                                                   (float4*)out_taste, nt);
}

// round 9
// speedup vs baseline: 1.5478x; 1.5478x over previous
#include <cuda_runtime.h>
#include <math.h>

#define HID 128
#define NI_MAX 20000
#define NT_MAX 100000
#define NE_MAX 600000
#define NB_MAX 512          // max CSR scan blocks (nt/256 <= 391)

// ---------------- scratch (device globals; no allocation allowed) ----------
__device__ float g_hs[NI_MAX * HID];   // projected ingredient features
__device__ float g_asrc[NI_MAX];       // per-src attention logit part
__device__ int   g_srcs[NE_MAX];       // CSR: source node per slot (dst-grouped)
__device__ int   g_deg[NT_MAX];        // in-degree per dst
__device__ int   g_off[NT_MAX + 1];    // CSR offsets
__device__ int   g_cursor[NT_MAX];     // fill cursors (absolute offsets)
__device__ int   g_bsum[NB_MAX];       // scan phase A partials
__device__ int   g_bbase[NB_MAX];      // scan phase B exclusive bases
__device__ float g_v[HID];             // W_taste^T @ att_dst
__device__ float g_c;                  // b_taste . att_dst
__device__ float g_colsum[HID];        // BN column sums
__device__ float g_colsq[HID];         // BN column sum of squares

// ---------------- init (+ fused v): zero counters; block 0 computes v ------
__global__ void k_initv(const float* __restrict__ Wt, const float* __restrict__ bt,
                        const float* __restrict__ att_dst, int nt) {
    if (blockIdx.x == 0) {
        int k = threadIdx.x;
        if (k < HID) {
            float s = 0.0f;
            #pragma unroll 8
            for (int j = 0; j < HID; j++) s += att_dst[j] * Wt[j * HID + k];
            g_v[k] = s;
            g_colsum[k] = 0.0f;
            g_colsq[k]  = 0.0f;
            if (k == 0) {
                float c = 0.0f;
                for (int j = 0; j < HID; j++) c += att_dst[j] * bt[j];
                g_c = c;
            }
        }
        return;
    }
    int stride = (gridDim.x - 1) * blockDim.x;
    for (int i = (blockIdx.x - 1) * blockDim.x + threadIdx.x; i < nt; i += stride)
        g_deg[i] = 0;
}

// ---------------- hs GEMM (vector-LDS) + fused a_src + fused edge count ----
// hs blocks: blockDim=128, 16 rows/block, LDS.128 tiles padded to 36 floats.
// count blocks (bid >= hs_b): 128 threads, per-edge atomicAdd into g_deg.
__global__ void k_hs_count(const float* __restrict__ x, const float* __restrict__ W,
                           const float* __restrict__ b, const float* __restrict__ att_src,
                           const int* __restrict__ edst,
                           int ni, int ne, int hs_b) {
    if ((int)blockIdx.x >= hs_b) {
        int i = (blockIdx.x - hs_b) * 128 + threadIdx.x;
        if (i < ne) atomicAdd(&g_deg[edst[i]], 1);
        return;
    }
    __shared__ float Ws[128][36];
    __shared__ float xs[16][36];
    __shared__ float red[4][16];
    const int c = threadIdx.x;
    const int row0 = blockIdx.x * 16;
    float acc[16];
    #pragma unroll
    for (int r = 0; r < 16; r++) acc[r] = 0.0f;

    for (int kt = 0; kt < 4; kt++) {
        #pragma unroll
        for (int i = 0; i < 32; i++) {
            int idx = i * 128 + c;
            int cc = idx >> 5, kk = idx & 31;
            Ws[cc][kk] = W[cc * HID + kt * 32 + kk];
        }
        #pragma unroll
        for (int i = 0; i < 4; i++) {
            int idx = i * 128 + c;
            int r = idx >> 5, kk = idx & 31;
            int row = row0 + r;
            xs[r][kk] = (row < ni) ? x[row * HID + kt * 32 + kk] : 0.0f;
        }
        __syncthreads();
        float4 w[8];
        #pragma unroll
        for (int k4 = 0; k4 < 8; k4++)
            w[k4] = *reinterpret_cast<const float4*>(&Ws[c][k4 * 4]);
        #pragma unroll
        for (int k4 = 0; k4 < 8; k4++) {
            float4 ww = w[k4];
            #pragma unroll
            for (int r = 0; r < 16; r++) {
                float4 xv = *reinterpret_cast<const float4*>(&xs[r][k4 * 4]);
                acc[r] += xv.x * ww.x + xv.y * ww.y + xv.z * ww.z + xv.w * ww.w;
            }
        }
        __syncthreads();
    }
    const float bb = b[c];
    const float as = att_src[c];
    const int lane = c & 31, wid = c >> 5;
    #pragma unroll
    for (int r = 0; r < 16; r++) {
        int row = row0 + r;
        float val = acc[r] + bb;
        if (row < ni) g_hs[row * HID + c] = val;
        float s = val * as;
        #pragma unroll
        for (int o = 16; o; o >>= 1) s += __shfl_xor_sync(0xffffffffu, s, o);
        if (lane == 0) red[wid][r] = s;
    }
    __syncthreads();
    if (c < 16) {
        int row = row0 + c;
        if (row < ni)
            g_asrc[row] = red[0][c] + red[1][c] + red[2][c] + red[3][c];
    }
}

// ---------------- CSR scan phase A: per-block (256) degree sums -------------
__global__ void k_scanA(int nt) {
    __shared__ int sh[256];
    int i = blockIdx.x * 256 + threadIdx.x;
    sh[threadIdx.x] = (i < nt) ? g_deg[i] : 0;
    __syncthreads();
    for (int o = 128; o; o >>= 1) {
        if (threadIdx.x < o) sh[threadIdx.x] += sh[threadIdx.x + o];
        __syncthreads();
    }
    if (threadIdx.x == 0) g_bsum[blockIdx.x] = sh[0];
}

// ---------------- CSR scan phase B: scan partials (1 block, 512) ------------
__global__ void k_scanB(int nb, int nt) {
    __shared__ int sh[NB_MAX];
    int t = threadIdx.x;
    int v = (t < nb) ? g_bsum[t] : 0;
    sh[t] = v;
    __syncthreads();
    for (int o = 1; o < NB_MAX; o <<= 1) {
        int u = (t >= o) ? sh[t - o] : 0;
        __syncthreads();
        sh[t] += u;
        __syncthreads();
    }
    if (t < nb) g_bbase[t] = sh[t] - v;   // exclusive base
    if (t == nb - 1) g_off[nt] = sh[t];   // total edge count sentinel
}

// ---------------- CSR scan phase C: block scan + base -> offsets ------------
__global__ void k_scanC(int nt) {
    __shared__ int sh[256];
    int i = blockIdx.x * 256 + threadIdx.x;
    int t = threadIdx.x;
    int v = (i < nt) ? g_deg[i] : 0;
    sh[t] = v;
    __syncthreads();
    for (int o = 1; o < 256; o <<= 1) {
        int u = (t >= o) ? sh[t - o] : 0;
        __syncthreads();
        sh[t] += u;
        __syncthreads();
    }
    if (i < nt) {
        int off = g_bbase[blockIdx.x] + sh[t] - v;
        g_off[i]    = off;
        g_cursor[i] = off;
    }
}

// ---------------- CSR fill: cursor holds absolute offset --------------------
__global__ void k_fill(const int* __restrict__ src, const int* __restrict__ dst, int ne) {
    int i = blockIdx.x * blockDim.x + threadIdx.x;
    if (i >= ne) return;
    int slot = atomicAdd(&g_cursor[dst[i]], 1);
    g_srcs[slot] = src[i];
}

// ---------------- mega: per-dst softmax + aggregate + relu + residual + BN --
// Persistent grid-stride, 8 warps/block, one dst per warp per iteration.
// Next iteration's x_taste row + CSR offsets are prefetched before the body.
// Softmax shift-invariance: logits bounded (~|9|), exp safe without max-sub.
#define MEGA_WARPS 8
#define MEGA_BLOCKS 1184
__global__ void k_mega(const float* __restrict__ x_taste,
                       float* __restrict__ out_taste, int nt) {
    __shared__ float4 ssum[MEGA_WARPS][32];
    __shared__ float4 ssq[MEGA_WARPS][32];
    const int lane = threadIdx.x & 31;
    const int wid  = threadIdx.x >> 5;
    const int gw   = blockIdx.x * MEGA_WARPS + wid;
    const int nw   = gridDim.x * MEGA_WARPS;

    const float4* __restrict__ hs4 = reinterpret_cast<const float4*>(g_hs) + lane;
    const float4* __restrict__ xt4 = reinterpret_cast<const float4*>(x_taste) + lane;
    const float4 vv = reinterpret_cast<const float4*>(g_v)[lane];
    const float  cc = g_c;

    float4 bsum = make_float4(0.f, 0.f, 0.f, 0.f);
    float4 bsq  = make_float4(0.f, 0.f, 0.f, 0.f);

    int d = gw;
    float4 xt_n = make_float4(0.f, 0.f, 0.f, 0.f);
    int beg_n = 0, end_n = 0;
    if (d < nt) {
        xt_n  = xt4[(size_t)d * (HID / 4)];
        beg_n = g_off[d];
        end_n = g_off[d + 1];
    }

    for (; d < nt; d += nw) {
        const float4 xt = xt_n;
        const int beg = beg_n;
        const int deg = end_n - beg_n;
        const int dn = d + nw;
        if (dn < nt) {                      // prefetch next iteration
            xt_n  = xt4[(size_t)dn * (HID / 4)];
            beg_n = g_off[dn];
            end_n = g_off[dn + 1];
        }

        // a_dst = x_taste[d] . v + c
        float ad = xt.x * vv.x + xt.y * vv.y + xt.z * vv.z + xt.w * vv.w;
        #pragma unroll
        for (int o = 16; o; o >>= 1) ad += __shfl_xor_sync(0xffffffffu, ad, o);
        ad += cc;

        float4 acc = make_float4(0.f, 0.f, 0.f, 0.f);

        if (deg <= 32) {
            // register-resident path (covers ~all nodes; mean degree ~6)
            int   s  = 0;
            float ev = 0.0f;
            if (lane < deg) {
                s = g_srcs[beg + lane];
                float a = g_asrc[s] + ad;
                a = (a >= 0.0f) ? a : 0.2f * a;      // leaky_relu(0.2)
                ev = expf(a);
            }
            float denom = ev;
            #pragma unroll
            for (int o = 16; o; o >>= 1) denom += __shfl_xor_sync(0xffffffffu, denom, o);
            const float inv = 1.0f / (denom + 1e-16f);

            int j = 0;
            for (; j + 4 <= deg; j += 4) {
                float w0 = __shfl_sync(0xffffffffu, ev, j + 0) * inv;
                float w1 = __shfl_sync(0xffffffffu, ev, j + 1) * inv;
                float w2 = __shfl_sync(0xffffffffu, ev, j + 2) * inv;
                float w3 = __shfl_sync(0xffffffffu, ev, j + 3) * inv;
                int   s0 = __shfl_sync(0xffffffffu, s, j + 0);
                int   s1 = __shfl_sync(0xffffffffu, s, j + 1);
                int   s2 = __shfl_sync(0xffffffffu, s, j + 2);
                int   s3 = __shfl_sync(0xffffffffu, s, j + 3);
                float4 h0 = hs4[(size_t)s0 * (HID / 4)];
                float4 h1 = hs4[(size_t)s1 * (HID / 4)];
                float4 h2 = hs4[(size_t)s2 * (HID / 4)];
                float4 h3 = hs4[(size_t)s3 * (HID / 4)];
                acc.x += w0 * h0.x; acc.y += w0 * h0.y; acc.z += w0 * h0.z; acc.w += w0 * h0.w;
                acc.x += w1 * h1.x; acc.y += w1 * h1.y; acc.z += w1 * h1.z; acc.w += w1 * h1.w;
                acc.x += w2 * h2.x; acc.y += w2 * h2.y; acc.z += w2 * h2.z; acc.w += w2 * h2.w;
                acc.x += w3 * h3.x; acc.y += w3 * h3.y; acc.z += w3 * h3.z; acc.w += w3 * h3.w;
            }
            for (; j < deg; j++) {
                float w  = __shfl_sync(0xffffffffu, ev, j) * inv;
                int   sj = __shfl_sync(0xffffffffu, s, j);
                float4 h = hs4[(size_t)sj * (HID / 4)];
                acc.x += w * h.x; acc.y += w * h.y;
                acc.z += w * h.z; acc.w += w * h.w;
            }
        } else {
            // rare fallback (deg > 32): recompute exp, broadcast loads
            float denom = 0.0f;
            for (int k = beg + lane; k < beg + deg; k += 32) {
                float a = g_asrc[g_srcs[k]] + ad;
                a = (a >= 0.0f) ? a : 0.2f * a;
                denom += expf(a);
            }
            #pragma unroll
            for (int o = 16; o; o >>= 1) denom += __shfl_xor_sync(0xffffffffu, denom, o);
            const float inv = 1.0f / (denom + 1e-16f);

            for (int k = beg; k < beg + deg; k++) {
                int sj = g_srcs[k];
                float a = g_asrc[sj] + ad;
                a = (a >= 0.0f) ? a : 0.2f * a;
                float w = expf(a) * inv;
                float4 h = hs4[(size_t)sj * (HID / 4)];
                acc.x += w * h.x; acc.y += w * h.y;
                acc.z += w * h.z; acc.w += w * h.w;
            }
        }

        // relu(agg) + residual, write
        float4 outv;
        outv.x = fmaxf(acc.x, 0.f) + xt.x;
        outv.y = fmaxf(acc.y, 0.f) + xt.y;
        outv.z = fmaxf(acc.z, 0.f) + xt.z;
        outv.w = fmaxf(acc.w, 0.f) + xt.w;
        reinterpret_cast<float4*>(out_taste + (size_t)d * HID)[lane] = outv;

        bsum.x += outv.x; bsum.y += outv.y; bsum.z += outv.z; bsum.w += outv.w;
        bsq.x += outv.x * outv.x; bsq.y += outv.y * outv.y;
        bsq.z += outv.z * outv.z; bsq.w += outv.w * outv.w;
    }

    // block-level BN reduce: one atomic set per block
    ssum[wid][lane] = bsum;
    ssq[wid][lane]  = bsq;
    __syncthreads();
    if (wid == 0) {
        float4 s = make_float4(0.f, 0.f, 0.f, 0.f);
        float4 q = make_float4(0.f, 0.f, 0.f, 0.f);
        #pragma unroll
        for (int i = 0; i < MEGA_WARPS; i++) {
            float4 a = ssum[i][lane], b = ssq[i][lane];
            s.x += a.x; s.y += a.y; s.z += a.z; s.w += a.w;
            q.x += b.x; q.y += b.y; q.z += b.z; q.w += b.w;
        }
        atomicAdd(&g_colsum[lane * 4 + 0], s.x);
        atomicAdd(&g_colsum[lane * 4 + 1], s.y);
        atomicAdd(&g_colsum[lane * 4 + 2], s.z);
        atomicAdd(&g_colsum[lane * 4 + 3], s.w);
        atomicAdd(&g_colsq[lane * 4 + 0], q.x);
        atomicAdd(&g_colsq[lane * 4 + 1], q.y);
        atomicAdd(&g_colsq[lane * 4 + 2], q.z);
        atomicAdd(&g_colsq[lane * 4 + 3], q.w);
    }
}

// ---------------- taste pass B: BN normalize + affine + relu ---------------
#define ROWS_B 128
__global__ void k_tasteB(const float* __restrict__ gamma, const float* __restrict__ beta,
                         float4* __restrict__ out4, int nt) {
    const int f4 = threadIdx.x & 31;
    const int rl = threadIdx.x >> 5;
    const float inv_n = 1.0f / (float)nt;
    float mean[4], scale[4], bet[4];
    #pragma unroll
    for (int k = 0; k < 4; k++) {
        int f = f4 * 4 + k;
        float m = g_colsum[f] * inv_n;
        float var = g_colsq[f] * inv_n - m * m;
        mean[k] = m;
        scale[k] = rsqrtf(var + 1e-5f) * gamma[f];
        bet[k] = beta[f];
    }
    const int rend = min(blockIdx.x * ROWS_B + ROWS_B, nt);
    for (int r = blockIdx.x * ROWS_B + rl; r < rend; r += 8) {
        int idx = r * (HID / 4) + f4;
        float4 v = out4[idx];
        v.x = fmaxf((v.x - mean[0]) * scale[0] + bet[0], 0.f);
        v.y = fmaxf((v.y - mean[1]) * scale[1] + bet[1], 0.f);
        v.z = fmaxf((v.z - mean[2]) * scale[2] + bet[2], 0.f);
        v.w = fmaxf((v.w - mean[3]) * scale[3] + bet[3], 0.f);
        out4[idx] = v;
    }
}

// ---------------- launch ---------------------------------------------------
extern "C" void kernel_launch(void* const* d_in, const int* in_sizes, int n_in,
                              void* d_out, int out_size) {
    const float* x_ing   = (const float*)d_in[0];
    const float* x_taste = (const float*)d_in[1];
    const int*   esrc    = (const int*)d_in[2];
    const int*   edst    = (const int*)d_in[3];
    const float* Wi      = (const float*)d_in[4];
    const float* bi      = (const float*)d_in[5];
    const float* Wt      = (const float*)d_in[6];
    const float* bt      = (const float*)d_in[7];
    const float* att_src = (const float*)d_in[8];
    const float* att_dst = (const float*)d_in[9];
    // d_in[10..12] = k_lin_w, k_lin_b, q_sem: provably unused (beta == 1)
    const float* gamma   = (const float*)d_in[13];
    const float* beta    = (const float*)d_in[14];

    const int ni = in_sizes[0] / HID;
    const int nt = in_sizes[1] / HID;
    const int ne = in_sizes[2];

    float* out       = (float*)d_out;
    float* out_taste = out + (size_t)ni * HID;

    // ingredient passthrough
    cudaMemcpyAsync(out, x_ing, (size_t)ni * HID * sizeof(float),
                    cudaMemcpyDeviceToDevice);

    const int hs_b  = (ni + 15) / 16;
    const int cnt_b = (ne + 127) / 128;
    const int nb    = (nt + 255) / 256;

    k_initv   <<<400, 256>>> (Wt, bt, att_dst, nt);
    k_hs_count<<<hs_b + cnt_b, 128>>> (x_ing, Wi, bi, att_src, edst, ni, ne, hs_b);
    k_scanA   <<<nb, 256>>> (nt);
    k_scanB   <<<1, NB_MAX>>> (nb, nt);
    k_scanC   <<<nb, 256>>> (nt);
    k_fill    <<<(ne + 255) / 256, 256>>> (esrc, edst, ne);
    k_mega    <<<MEGA_BLOCKS, 256>>> (x_taste, out_taste, nt);
    k_tasteB  <<<(nt + ROWS_B - 1) / ROWS_B, 256>>> (gamma, beta,
                                                     (float4*)out_taste, nt);
}

// round 13
// speedup vs baseline: 1.5522x; 1.0028x over previous
#include <cuda_runtime.h>
#include <math.h>

#define HID 128
#define NI_MAX 20000
#define NT_MAX 100000
#define NE_MAX 600000
#define NB_MAX 512          // max CSR scan blocks (nt/256 <= 391)

// ---------------- scratch (device globals; no allocation allowed) ----------
// NOTE: g_deg relies on zero-init at module load for the FIRST call; every
// call leaves it zeroed again (k_scan zeroes after consuming) -> each
// invocation sees identical entry state (deterministic, graph-replay safe).
// g_bpub is zeroed by k_front's v-block each call (k_front completes before
// k_scan launches).
__device__ float g_hs[NI_MAX * HID];   // projected ingredient features
__device__ float g_asrc[NI_MAX];       // per-src attention logit part
__device__ int   g_srcs[NE_MAX];       // CSR: source node per slot (dst-grouped)
__device__ int   g_deg[NT_MAX];        // in-degree per dst (zero at entry)
__device__ int   g_off[NT_MAX + 1];    // CSR offsets
__device__ int   g_cursor[NT_MAX];     // fill cursors (absolute offsets)
// packed publication word: high 32 = flag (1), low 32 = block aggregate.
// single 64-bit volatile load on the consumer side -> no ordering hazard.
__device__ volatile unsigned long long g_bpub[NB_MAX];
__device__ float g_v[HID];             // W_taste^T @ att_dst
__device__ float g_c;                  // b_taste . att_dst
__device__ float g_colsum[HID];        // BN column sums
__device__ float g_colsq[HID];         // BN column sum of squares

// ---- fused front kernel: hs GEMM + a_src | edge count | passthrough | v ----
// grid = hs_b (GEMM) + cnt_b (count) + cpy_b (ingredient copy) + 1 (v/c/BN0)
__global__ void k_front(const float* __restrict__ x, const float* __restrict__ W,
                        const float* __restrict__ b, const float* __restrict__ att_src,
                        const int* __restrict__ edst,
                        const float* __restrict__ Wt, const float* __restrict__ bt,
                        const float* __restrict__ att_dst,
                        float* __restrict__ out_ing,
                        int ni, int ne, int hs_b, int cnt_b, int cpy_b) {
    const int bid = blockIdx.x;
    if (bid >= hs_b) {
        if (bid < hs_b + cnt_b) {
            // ---- edge-count role ----
            int i = (bid - hs_b) * 128 + threadIdx.x;
            if (i < ne) atomicAdd(&g_deg[edst[i]], 1);
        } else if (bid < hs_b + cnt_b + cpy_b) {
            // ---- ingredient passthrough role ----
            const float4* __restrict__ s4 = (const float4*)x;
            float4* __restrict__ d4 = (float4*)out_ing;
            int total = ni * (HID / 4);
            int stride = cpy_b * 128;
            for (int i = (bid - hs_b - cnt_b) * 128 + threadIdx.x; i < total; i += stride)
                d4[i] = s4[i];
        } else {
            // ---- v / c / BN-zero / scan-pub-zero role (one block, 128) ----
            int k = threadIdx.x;
            if (k < HID) {
                float s = 0.0f;
                #pragma unroll 8
                for (int j = 0; j < HID; j++) s += att_dst[j] * Wt[j * HID + k];
                g_v[k] = s;
                g_colsum[k] = 0.0f;
                g_colsq[k]  = 0.0f;
                if (k == 0) {
                    float c = 0.0f;
                    for (int j = 0; j < HID; j++) c += att_dst[j] * bt[j];
                    g_c = c;
                }
            }
            #pragma unroll
            for (int r = 0; r < NB_MAX / 128; r++)
                g_bpub[r * 128 + k] = 0ull;
        }
        return;
    }
    // ---- hs GEMM role: blockDim=128, 16 rows/block, vector-LDS tiles ----
    __shared__ float Ws[128][36];
    __shared__ float xs[16][36];
    __shared__ float red[4][16];
    const int c = threadIdx.x;
    const int row0 = bid * 16;
    float acc[16];
    #pragma unroll
    for (int r = 0; r < 16; r++) acc[r] = 0.0f;

    for (int kt = 0; kt < 4; kt++) {
        #pragma unroll
        for (int i = 0; i < 32; i++) {
            int idx = i * 128 + c;
            int cc = idx >> 5, kk = idx & 31;
            Ws[cc][kk] = W[cc * HID + kt * 32 + kk];
        }
        #pragma unroll
        for (int i = 0; i < 4; i++) {
            int idx = i * 128 + c;
            int r = idx >> 5, kk = idx & 31;
            int row = row0 + r;
            xs[r][kk] = (row < ni) ? x[row * HID + kt * 32 + kk] : 0.0f;
        }
        __syncthreads();
        float4 w[8];
        #pragma unroll
        for (int k4 = 0; k4 < 8; k4++)
            w[k4] = *reinterpret_cast<const float4*>(&Ws[c][k4 * 4]);
        #pragma unroll
        for (int k4 = 0; k4 < 8; k4++) {
            float4 ww = w[k4];
            #pragma unroll
            for (int r = 0; r < 16; r++) {
                float4 xv = *reinterpret_cast<const float4*>(&xs[r][k4 * 4]);
                acc[r] += xv.x * ww.x + xv.y * ww.y + xv.z * ww.z + xv.w * ww.w;
            }
        }
        __syncthreads();
    }
    const float bb = b[c];
    const float as = att_src[c];
    const int lane = c & 31, wid = c >> 5;
    #pragma unroll
    for (int r = 0; r < 16; r++) {
        int row = row0 + r;
        float val = acc[r] + bb;
        if (row < ni) g_hs[row * HID + c] = val;
        float s = val * as;
        #pragma unroll
        for (int o = 16; o; o >>= 1) s += __shfl_xor_sync(0xffffffffu, s, o);
        if (lane == 0) red[wid][r] = s;
    }
    __syncthreads();
    if (c < 16) {
        int row = row0 + c;
        if (row < ni)
            g_asrc[row] = red[0][c] + red[1][c] + red[2][c] + red[3][c];
    }
}

// ---- CSR scan (single kernel): publish aggregate -> spin-sum preds -> scan -
// All nb (<=391) blocks of 256 threads are co-resident in wave 1 (k_scan is
// tiny: ~20 regs, 1KB smem -> 8 blocks/SM trivially; 391 << 148*8), so
// spin-waiting on lower-indexed blocks' published words cannot deadlock.
// Publication is a single 64-bit word (flag<<32 | aggregate): one volatile
// load observes both atomically -> no consumer-side ordering hazard.
__global__ void k_scan(int nt) {
    __shared__ int sh[256];
    const int t = threadIdx.x;
    const int bid = blockIdx.x;
    const int i = bid * 256 + t;
    const int v = (i < nt) ? g_deg[i] : 0;

    // phase 1: block aggregate, publish (flag|value in one word)
    sh[t] = v;
    __syncthreads();
    #pragma unroll
    for (int o = 128; o; o >>= 1) {
        if (t < o) sh[t] += sh[t + o];
        __syncthreads();
    }
    if (t == 0) {
        unsigned long long pub = (1ull << 32) | (unsigned int)sh[0];
        g_bpub[bid] = pub;          // volatile store, single word
        __threadfence();
    }

    // phase 2: sum predecessors' aggregates (spin until published)
    int partial = 0;
    for (int p = t; p < bid; p += 256) {
        unsigned long long w;
        while (((w = g_bpub[p]) >> 32) == 0ull) __nanosleep(40);
        partial += (int)(unsigned int)w;
    }
    __syncthreads();           // everyone done with phase-1 sh[] use
    sh[t] = partial;
    __syncthreads();
    #pragma unroll
    for (int o = 128; o; o >>= 1) {
        if (t < o) sh[t] += sh[t + o];
        __syncthreads();
    }
    const int base = sh[0];
    __syncthreads();

    // phase 3: block-local inclusive scan of degrees -> offsets
    sh[t] = v;
    __syncthreads();
    for (int o = 1; o < 256; o <<= 1) {
        int u = (t >= o) ? sh[t - o] : 0;
        __syncthreads();
        sh[t] += u;
        __syncthreads();
    }
    if (i < nt) {
        int off = base + sh[t] - v;      // exclusive offset
        g_off[i]    = off;
        g_cursor[i] = off;
        g_deg[i]    = 0;                 // ready for next invocation
        if (i == nt - 1) g_off[nt] = off + v;   // total-edges sentinel
    }
}

// ---------------- CSR fill: cursor holds absolute offset --------------------
__global__ void k_fill(const int* __restrict__ src, const int* __restrict__ dst, int ne) {
    int i = blockIdx.x * blockDim.x + threadIdx.x;
    if (i >= ne) return;
    int slot = atomicAdd(&g_cursor[dst[i]], 1);
    g_srcs[slot] = src[i];
}

// ---------------- mega: per-dst softmax + aggregate + relu + residual + BN --
// Persistent grid-stride, 8 warps/block, one dst per warp per iteration.
// Next iteration's x_taste row + CSR offsets are prefetched before the body.
// Softmax shift-invariance: logits bounded (~|9|), exp safe without max-sub.
#define MEGA_WARPS 8
#define MEGA_BLOCKS 1184
__global__ void k_mega(const float* __restrict__ x_taste,
                       float* __restrict__ out_taste, int nt) {
    __shared__ float4 ssum[MEGA_WARPS][32];
    __shared__ float4 ssq[MEGA_WARPS][32];
    const int lane = threadIdx.x & 31;
    const int wid  = threadIdx.x >> 5;
    const int gw   = blockIdx.x * MEGA_WARPS + wid;
    const int nw   = gridDim.x * MEGA_WARPS;

    const float4* __restrict__ hs4 = reinterpret_cast<const float4*>(g_hs) + lane;
    const float4* __restrict__ xt4 = reinterpret_cast<const float4*>(x_taste) + lane;
    const float4 vv = reinterpret_cast<const float4*>(g_v)[lane];
    const float  cc = g_c;

    float4 bsum = make_float4(0.f, 0.f, 0.f, 0.f);
    float4 bsq  = make_float4(0.f, 0.f, 0.f, 0.f);

    int d = gw;
    float4 xt_n = make_float4(0.f, 0.f, 0.f, 0.f);
    int beg_n = 0, end_n = 0;
    if (d < nt) {
        xt_n  = xt4[(size_t)d * (HID / 4)];
        beg_n = g_off[d];
        end_n = g_off[d + 1];
    }

    for (; d < nt; d += nw) {
        const float4 xt = xt_n;
        const int beg = beg_n;
        const int deg = end_n - beg_n;
        const int dn = d + nw;
        if (dn < nt) {                      // prefetch next iteration
            xt_n  = xt4[(size_t)dn * (HID / 4)];
            beg_n = g_off[dn];
            end_n = g_off[dn + 1];
        }

        // a_dst = x_taste[d] . v + c
        float ad = xt.x * vv.x + xt.y * vv.y + xt.z * vv.z + xt.w * vv.w;
        #pragma unroll
        for (int o = 16; o; o >>= 1) ad += __shfl_xor_sync(0xffffffffu, ad, o);
        ad += cc;

        float4 acc = make_float4(0.f, 0.f, 0.f, 0.f);

        if (deg <= 32) {
            // register-resident path (covers ~all nodes; mean degree ~6)
            int   s  = 0;
            float ev = 0.0f;
            if (lane < deg) {
                s = g_srcs[beg + lane];
                float a = g_asrc[s] + ad;
                a = (a >= 0.0f) ? a : 0.2f * a;      // leaky_relu(0.2)
                ev = expf(a);
            }
            float denom = ev;
            #pragma unroll
            for (int o = 16; o; o >>= 1) denom += __shfl_xor_sync(0xffffffffu, denom, o);
            const float inv = 1.0f / (denom + 1e-16f);

            int j = 0;
            for (; j + 4 <= deg; j += 4) {
                float w0 = __shfl_sync(0xffffffffu, ev, j + 0) * inv;
                float w1 = __shfl_sync(0xffffffffu, ev, j + 1) * inv;
                float w2 = __shfl_sync(0xffffffffu, ev, j + 2) * inv;
                float w3 = __shfl_sync(0xffffffffu, ev, j + 3) * inv;
                int   s0 = __shfl_sync(0xffffffffu, s, j + 0);
                int   s1 = __shfl_sync(0xffffffffu, s, j + 1);
                int   s2 = __shfl_sync(0xffffffffu, s, j + 2);
                int   s3 = __shfl_sync(0xffffffffu, s, j + 3);
                float4 h0 = hs4[(size_t)s0 * (HID / 4)];
                float4 h1 = hs4[(size_t)s1 * (HID / 4)];
                float4 h2 = hs4[(size_t)s2 * (HID / 4)];
                float4 h3 = hs4[(size_t)s3 * (HID / 4)];
                acc.x += w0 * h0.x; acc.y += w0 * h0.y; acc.z += w0 * h0.z; acc.w += w0 * h0.w;
                acc.x += w1 * h1.x; acc.y += w1 * h1.y; acc.z += w1 * h1.z; acc.w += w1 * h1.w;
                acc.x += w2 * h2.x; acc.y += w2 * h2.y; acc.z += w2 * h2.z; acc.w += w2 * h2.w;
                acc.x += w3 * h3.x; acc.y += w3 * h3.y; acc.z += w3 * h3.z; acc.w += w3 * h3.w;
            }
            for (; j < deg; j++) {
                float w  = __shfl_sync(0xffffffffu, ev, j) * inv;
                int   sj = __shfl_sync(0xffffffffu, s, j);
                float4 h = hs4[(size_t)sj * (HID / 4)];
                acc.x += w * h.x; acc.y += w * h.y;
                acc.z += w * h.z; acc.w += w * h.w;
            }
        } else {
            // rare fallback (deg > 32): recompute exp, broadcast loads
            float denom = 0.0f;
            for (int k = beg + lane; k < beg + deg; k += 32) {
                float a = g_asrc[g_srcs[k]] + ad;
                a = (a >= 0.0f) ? a : 0.2f * a;
                denom += expf(a);
            }
            #pragma unroll
            for (int o = 16; o; o >>= 1) denom += __shfl_xor_sync(0xffffffffu, denom, o);
            const float inv = 1.0f / (denom + 1e-16f);

            for (int k = beg; k < beg + deg; k++) {
                int sj = g_srcs[k];
                float a = g_asrc[sj] + ad;
                a = (a >= 0.0f) ? a : 0.2f * a;
                float w = expf(a) * inv;
                float4 h = hs4[(size_t)sj * (HID / 4)];
                acc.x += w * h.x; acc.y += w * h.y;
                acc.z += w * h.z; acc.w += w * h.w;
            }
        }

        // relu(agg) + residual, write
        float4 outv;
        outv.x = fmaxf(acc.x, 0.f) + xt.x;
        outv.y = fmaxf(acc.y, 0.f) + xt.y;
        outv.z = fmaxf(acc.z, 0.f) + xt.z;
        outv.w = fmaxf(acc.w, 0.f) + xt.w;
        reinterpret_cast<float4*>(out_taste + (size_t)d * HID)[lane] = outv;

        bsum.x += outv.x; bsum.y += outv.y; bsum.z += outv.z; bsum.w += outv.w;
        bsq.x += outv.x * outv.x; bsq.y += outv.y * outv.y;
        bsq.z += outv.z * outv.z; bsq.w += outv.w * outv.w;
    }

    // block-level BN reduce: one atomic set per block
    ssum[wid][lane] = bsum;
    ssq[wid][lane]  = bsq;
    __syncthreads();
    if (wid == 0) {
        float4 s = make_float4(0.f, 0.f, 0.f, 0.f);
        float4 q = make_float4(0.f, 0.f, 0.f, 0.f);
        #pragma unroll
        for (int i = 0; i < MEGA_WARPS; i++) {
            float4 a = ssum[i][lane], b = ssq[i][lane];
            s.x += a.x; s.y += a.y; s.z += a.z; s.w += a.w;
            q.x += b.x; q.y += b.y; q.z += b.z; q.w += b.w;
        }
        atomicAdd(&g_colsum[lane * 4 + 0], s.x);
        atomicAdd(&g_colsum[lane * 4 + 1], s.y);
        atomicAdd(&g_colsum[lane * 4 + 2], s.z);
        atomicAdd(&g_colsum[lane * 4 + 3], s.w);
        atomicAdd(&g_colsq[lane * 4 + 0], q.x);
        atomicAdd(&g_colsq[lane * 4 + 1], q.y);
        atomicAdd(&g_colsq[lane * 4 + 2], q.z);
        atomicAdd(&g_colsq[lane * 4 + 3], q.w);
    }
}

// ---------------- taste pass B: BN normalize + affine + relu ---------------
#define ROWS_B 128
__global__ void k_tasteB(const float* __restrict__ gamma, const float* __restrict__ beta,
                         float4* __restrict__ out4, int nt) {
    const int f4 = threadIdx.x & 31;
    const int rl = threadIdx.x >> 5;
    const float inv_n = 1.0f / (float)nt;
    float mean[4], scale[4], bet[4];
    #pragma unroll
    for (int k = 0; k < 4; k++) {
        int f = f4 * 4 + k;
        float m = g_colsum[f] * inv_n;
        float var = g_colsq[f] * inv_n - m * m;
        mean[k] = m;
        scale[k] = rsqrtf(var + 1e-5f) * gamma[f];
        bet[k] = beta[f];
    }
    const int rend = min(blockIdx.x * ROWS_B + ROWS_B, nt);
    for (int r = blockIdx.x * ROWS_B + rl; r < rend; r += 8) {
        int idx = r * (HID / 4) + f4;
        float4 v = out4[idx];
        v.x = fmaxf((v.x - mean[0]) * scale[0] + bet[0], 0.f);
        v.y = fmaxf((v.y - mean[1]) * scale[1] + bet[1], 0.f);
        v.z = fmaxf((v.z - mean[2]) * scale[2] + bet[2], 0.f);
        v.w = fmaxf((v.w - mean[3]) * scale[3] + bet[3], 0.f);
        out4[idx] = v;
    }
}

// ---------------- launch ---------------------------------------------------
extern "C" void kernel_launch(void* const* d_in, const int* in_sizes, int n_in,
                              void* d_out, int out_size) {
    const float* x_ing   = (const float*)d_in[0];
    const float* x_taste = (const float*)d_in[1];
    const int*   esrc    = (const int*)d_in[2];
    const int*   edst    = (const int*)d_in[3];
    const float* Wi      = (const float*)d_in[4];
    const float* bi      = (const float*)d_in[5];
    const float* Wt      = (const float*)d_in[6];
    const float* bt      = (const float*)d_in[7];
    const float* att_src = (const float*)d_in[8];
    const float* att_dst = (const float*)d_in[9];
    // d_in[10..12] = k_lin_w, k_lin_b, q_sem: provably unused (beta == 1)
    const float* gamma   = (const float*)d_in[13];
    const float* beta    = (const float*)d_in[14];

    const int ni = in_sizes[0] / HID;
    const int nt = in_sizes[1] / HID;
    const int ne = in_sizes[2];

    float* out       = (float*)d_out;
    float* out_taste = out + (size_t)ni * HID;

    const int hs_b  = (ni + 15) / 16;
    const int cnt_b = (ne + 127) / 128;
    const int cpy_b = 625;
    const int nb    = (nt + 255) / 256;

    k_front <<<hs_b + cnt_b + cpy_b + 1, 128>>> (x_ing, Wi, bi, att_src, edst,
                                                 Wt, bt, att_dst, out,
                                                 ni, ne, hs_b, cnt_b, cpy_b);
    k_scan  <<<nb, 256>>> (nt);
    k_fill  <<<(ne + 255) / 256, 256>>> (esrc, edst, ne);
    k_mega  <<<MEGA_BLOCKS, 256>>> (x_taste, out_taste, nt);
    k_tasteB<<<(nt + ROWS_B - 1) / ROWS_B, 256>>> (gamma, beta,
                                                   (float4*)out_taste, nt);
}